// round 9
// baseline (speedup 1.0000x reference)
#include <cuda_runtime.h>
#include <cuda_bf16.h>
#include <cstdint>

// Nearest-of-16-sorted-qpoints quantizer, round 7.
// Evidence R2-R6: DRAM pinned 75-78%, ~78us kernel regardless of LSU mix ->
// pure HBM mixed-stream bound (~6.9 TB/s achieved = 86% spec).
// R7: persistent grid (148 SM x 8 CTA = 1184 blocks, zero wave transitions)
// + grid-stride loop with one-iteration-ahead double buffering (one 256-bit
// load always in flight per thread). Quantizer: proven 4-level LDS binary
// search (rel_err == 0 in all prior rounds). 256-bit ld/st (R6, fastest ncu).

__device__ __forceinline__ float quant1(float v, float m7,
                                        const float* __restrict__ s_mid,
                                        const float* __restrict__ s_qp)
{
    int i = (v > m7) ? 8 : 0;              // level 0: uniform register compare
    i += (v > s_mid[i + 3]) ? 4 : 0;       // level 1: LDS
    i += (v > s_mid[i + 1]) ? 2 : 0;       // level 2: LDS
    i += (v > s_mid[i]) ? 1 : 0;           // level 3: LDS
    return s_qp[i];                         // value LUT: LDS broadcast
}

struct V8 { float v0, v1, v2, v3, v4, v5, v6, v7; };

__device__ __forceinline__ V8 ldg256_cs(const float* p)
{
    V8 r;
    asm volatile(
        "ld.global.cs.v8.f32 {%0,%1,%2,%3,%4,%5,%6,%7}, [%8];"
        : "=f"(r.v0), "=f"(r.v1), "=f"(r.v2), "=f"(r.v3),
          "=f"(r.v4), "=f"(r.v5), "=f"(r.v6), "=f"(r.v7)
        : "l"(p));
    return r;
}

__device__ __forceinline__ void stg256_cs(float* p, const V8& r)
{
    asm volatile(
        "st.global.cs.v8.f32 [%0], {%1,%2,%3,%4,%5,%6,%7,%8};"
        :: "l"(p),
           "f"(r.v0), "f"(r.v1), "f"(r.v2), "f"(r.v3),
           "f"(r.v4), "f"(r.v5), "f"(r.v6), "f"(r.v7)
        : "memory");
}

__device__ __forceinline__ V8 quant8(const V8& v, float m7,
                                     const float* __restrict__ s_mid,
                                     const float* __restrict__ s_qp)
{
    V8 o;
    o.v0 = quant1(v.v0, m7, s_mid, s_qp);
    o.v1 = quant1(v.v1, m7, s_mid, s_qp);
    o.v2 = quant1(v.v2, m7, s_mid, s_qp);
    o.v3 = quant1(v.v3, m7, s_mid, s_qp);
    o.v4 = quant1(v.v4, m7, s_mid, s_qp);
    o.v5 = quant1(v.v5, m7, s_mid, s_qp);
    o.v6 = quant1(v.v6, m7, s_mid, s_qp);
    o.v7 = quant1(v.v7, m7, s_mid, s_qp);
    return o;
}

__global__ __launch_bounds__(256) void QPointQuantize_kernel(
    const float* __restrict__ x,
    const float* __restrict__ q,
    float* __restrict__ out,
    int n)
{
    __shared__ float s_qp[16];
    __shared__ float s_mid[16];   // 15 used; banks 0-14, conflict-free

    if (threadIdx.x < 16)
        s_qp[threadIdx.x] = q[threadIdx.x];
    __syncthreads();
    if (threadIdx.x < 15)
        s_mid[threadIdx.x] = 0.5f * (s_qp[threadIdx.x] + s_qp[threadIdx.x + 1]);
    __syncthreads();

    const float m7 = s_mid[7];

    // Persistent grid-stride over 32-byte chunks, one-iter-ahead prefetch.
    long long start  = (long long)(blockIdx.x * blockDim.x + threadIdx.x) * 8;
    long long stride = (long long)gridDim.x * blockDim.x * 8;
    long long nn     = n;

    if (start >= nn) return;

    V8 cur = ldg256_cs(x + start);
    long long i = start;

    for (long long j = start + stride; j < nn; j += stride) {
        V8 nxt = ldg256_cs(x + j);           // prefetch next chunk first
        V8 o = quant8(cur, m7, s_mid, s_qp); // then process current
        stg256_cs(out + i, o);
        cur = nxt;
        i = j;
    }
    stg256_cs(out + i, quant8(cur, m7, s_mid, s_qp));
}

extern "C" void kernel_launch(void* const* d_in, const int* in_sizes, int n_in,
                              void* d_out, int out_size)
{
    const float* x = (const float*)d_in[0];   // (64, 1024, 1024) fp32
    const float* q = (const float*)d_in[1];   // (16,) fp32 sorted
    float* out = (float*)d_out;

    int n = in_sizes[0];          // 67,108,864 (multiple of 8)

    // Persistent grid: 8 CTAs/SM x 148 SMs (152 on GB300; 148 is safe and
    // the extra SMs just take fewer loop iterations via the stride pattern).
    int threads = 256;
    int blocks = 148 * 8;         // 1184

    QPointQuantize_kernel<<<blocks, threads>>>(x, q, out, n);
}

// round 10
// speedup vs baseline: 1.2021x; 1.2021x over previous
#include <cuda_runtime.h>
#include <cuda_bf16.h>
#include <cstdint>

// Nearest-of-16-sorted-qpoints quantizer, round 8.
// Converged model: kernel is at the mixed read/write HBM ceiling
// (512 MiB / ~78us = ~6.9 TB/s demand; DRAM pipe pinned 78% across R2/R4/R6
// regardless of LSU mix; R3/R7 showed occupancy/locality regressions).
// R8 = R4's proven data path (2x float4/thread, 4-level LDS binary search,
// streaming hints, 32 regs) with 512-thread blocks: same 2048 thr/SM
// residency, half the CTA count -> lower scheduling overhead, same DRAM
// access pattern. Expect floor-holding ~78-81us.

__device__ __forceinline__ float quant1(float v, float m7,
                                        const float* __restrict__ s_mid,
                                        const float* __restrict__ s_qp)
{
    int i = (v > m7) ? 8 : 0;              // level 0: uniform register compare
    i += (v > s_mid[i + 3]) ? 4 : 0;       // level 1: LDS
    i += (v > s_mid[i + 1]) ? 2 : 0;       // level 2: LDS
    i += (v > s_mid[i]) ? 1 : 0;           // level 3: LDS
    return s_qp[i];                         // value LUT: LDS broadcast
}

__global__ __launch_bounds__(512) void QPointQuantize_kernel(
    const float4* __restrict__ x,
    const float* __restrict__ q,
    float4* __restrict__ out,
    int n4)
{
    __shared__ float s_qp[16];
    __shared__ float s_mid[16];   // 15 used; banks 0-14, conflict-free

    if (threadIdx.x < 16)
        s_qp[threadIdx.x] = q[threadIdx.x];
    __syncthreads();
    if (threadIdx.x < 15)
        s_mid[threadIdx.x] = 0.5f * (s_qp[threadIdx.x] + s_qp[threadIdx.x + 1]);
    __syncthreads();

    const float m7 = s_mid[7];    // uniform -> register, skips one LDS level

    // 2 float4 per thread, coalesced, front-batched loads (MLP_p1=2).
    int base = blockIdx.x * (512 * 2) + threadIdx.x;

    if (base + 512 < n4) {
        float4 v0 = __ldcs(&x[base]);
        float4 v1 = __ldcs(&x[base + 512]);

        float4 o0, o1;
        o0.x = quant1(v0.x, m7, s_mid, s_qp);
        o0.y = quant1(v0.y, m7, s_mid, s_qp);
        o0.z = quant1(v0.z, m7, s_mid, s_qp);
        o0.w = quant1(v0.w, m7, s_mid, s_qp);
        o1.x = quant1(v1.x, m7, s_mid, s_qp);
        o1.y = quant1(v1.y, m7, s_mid, s_qp);
        o1.z = quant1(v1.z, m7, s_mid, s_qp);
        o1.w = quant1(v1.w, m7, s_mid, s_qp);

        __stcs(&out[base],       o0);
        __stcs(&out[base + 512], o1);
    } else {
        for (int k = 0; k < 2; k++) {
            int idx = base + k * 512;
            if (idx < n4) {
                float4 v = __ldcs(&x[idx]);
                float4 o;
                o.x = quant1(v.x, m7, s_mid, s_qp);
                o.y = quant1(v.y, m7, s_mid, s_qp);
                o.z = quant1(v.z, m7, s_mid, s_qp);
                o.w = quant1(v.w, m7, s_mid, s_qp);
                __stcs(&out[idx], o);
            }
        }
    }
}

extern "C" void kernel_launch(void* const* d_in, const int* in_sizes, int n_in,
                              void* d_out, int out_size)
{
    const float* x = (const float*)d_in[0];   // (64, 1024, 1024) fp32
    const float* q = (const float*)d_in[1];   // (16,) fp32 sorted
    float* out = (float*)d_out;

    int n = in_sizes[0];          // 67,108,864
    int n4 = n >> 2;              // 16,777,216 float4s

    int threads = 512;
    int elems_per_block = threads * 2;                     // 1024 float4s
    int blocks = (n4 + elems_per_block - 1) / elems_per_block;  // 16,384

    QPointQuantize_kernel<<<blocks, threads>>>(
        (const float4*)x, q, (float4*)out, n4);
}

// round 12
// speedup vs baseline: 1.2351x; 1.0274x over previous
#include <cuda_runtime.h>
#include <cuda_bf16.h>
#include <cstdint>

// Nearest-of-16-sorted-qpoints quantizer, round 9 (floor-holding).
// Converged: 512 MiB r+w / ~78us kernel = ~6.9 TB/s -> mixed-stream HBM
// ceiling. R4 config (256 thr, 2x float4/thread, 4-level LDS binary search,
// cs hints, 32 regs, occ 86%) is the empirical optimum across 8 rounds.
// R9 = R4 with single-barrier smem init and straight-line hot path.

__device__ __forceinline__ float quant1(float v, float m7,
                                        const float* __restrict__ s_mid,
                                        const float* __restrict__ s_qp)
{
    int i = (v > m7) ? 8 : 0;              // level 0: uniform register compare
    i += (v > s_mid[i + 3]) ? 4 : 0;       // level 1: LDS
    i += (v > s_mid[i + 1]) ? 2 : 0;       // level 2: LDS
    i += (v > s_mid[i]) ? 1 : 0;           // level 3: LDS
    return s_qp[i];                         // value LUT: LDS broadcast
}

__global__ __launch_bounds__(256) void QPointQuantize_kernel(
    const float4* __restrict__ x,
    const float* __restrict__ q,
    float4* __restrict__ out,
    int n4)
{
    __shared__ float s_qp[16];
    __shared__ float s_mid[16];   // 15 used; banks 0-14, conflict-free

    // One-stage init straight from global q (16 B, L2-resident after warp 0).
    if (threadIdx.x < 16) {
        float qi = q[threadIdx.x];
        s_qp[threadIdx.x] = qi;
        if (threadIdx.x < 15)
            s_mid[threadIdx.x] = 0.5f * (qi + q[threadIdx.x + 1]);
    }
    __syncthreads();

    const float m7 = s_mid[7];    // uniform -> register, skips one LDS level

    // 2 float4 per thread, coalesced, front-batched loads (MLP_p1=2).
    int base = blockIdx.x * (256 * 2) + threadIdx.x;

    if (base + 256 < n4) {        // taken by every live block for this shape
        float4 v0 = __ldcs(&x[base]);
        float4 v1 = __ldcs(&x[base + 256]);

        float4 o0, o1;
        o0.x = quant1(v0.x, m7, s_mid, s_qp);
        o0.y = quant1(v0.y, m7, s_mid, s_qp);
        o0.z = quant1(v0.z, m7, s_mid, s_qp);
        o0.w = quant1(v0.w, m7, s_mid, s_qp);
        o1.x = quant1(v1.x, m7, s_mid, s_qp);
        o1.y = quant1(v1.y, m7, s_mid, s_qp);
        o1.z = quant1(v1.z, m7, s_mid, s_qp);
        o1.w = quant1(v1.w, m7, s_mid, s_qp);

        __stcs(&out[base],       o0);
        __stcs(&out[base + 256], o1);
    } else {
        // Cold tail fallback (unreached for 64x1024x1024, kept for safety)
        for (int k = 0; k < 2; k++) {
            int idx = base + k * 256;
            if (idx < n4) {
                float4 v = __ldcs(&x[idx]);
                float4 o;
                o.x = quant1(v.x, m7, s_mid, s_qp);
                o.y = quant1(v.y, m7, s_mid, s_qp);
                o.z = quant1(v.z, m7, s_mid, s_qp);
                o.w = quant1(v.w, m7, s_mid, s_qp);
                __stcs(&out[idx], o);
            }
        }
    }
}

extern "C" void kernel_launch(void* const* d_in, const int* in_sizes, int n_in,
                              void* d_out, int out_size)
{
    const float* x = (const float*)d_in[0];   // (64, 1024, 1024) fp32
    const float* q = (const float*)d_in[1];   // (16,) fp32 sorted
    float* out = (float*)d_out;

    int n = in_sizes[0];          // 67,108,864
    int n4 = n >> 2;              // 16,777,216 float4s

    int threads = 256;
    int elems_per_block = threads * 2;                     // 512 float4s
    int blocks = (n4 + elems_per_block - 1) / elems_per_block;  // 32,768

    QPointQuantize_kernel<<<blocks, threads>>>(
        (const float4*)x, q, (float4*)out, n4);
}

// round 13
// speedup vs baseline: 1.2361x; 1.0008x over previous
#include <cuda_runtime.h>
#include <cuda_bf16.h>
#include <cstdint>

// Nearest-of-16-sorted-qpoints quantizer, round 10 (final micro-trim).
// R9 = best (80.4us bench / 78.1us ncu, DRAM 77.9%): mixed-stream HBM floor.
// R10: identical config, but the streaming read uses L1::no_allocate
// (read-once data should not consume L1 allocation/tag bandwidth; L1 was
// at ~60% mostly from fill traffic). Stores keep .cs. Everything else
// byte-identical to the R9 winner.

__device__ __forceinline__ float quant1(float v, float m7,
                                        const float* __restrict__ s_mid,
                                        const float* __restrict__ s_qp)
{
    int i = (v > m7) ? 8 : 0;              // level 0: uniform register compare
    i += (v > s_mid[i + 3]) ? 4 : 0;       // level 1: LDS
    i += (v > s_mid[i + 1]) ? 2 : 0;       // level 2: LDS
    i += (v > s_mid[i]) ? 1 : 0;           // level 3: LDS
    return s_qp[i];                         // value LUT: LDS broadcast
}

// 128-bit streaming load that does not allocate in L1.
__device__ __forceinline__ float4 ldg128_noL1(const float4* p)
{
    float4 r;
    asm volatile(
        "ld.global.L1::no_allocate.v4.f32 {%0,%1,%2,%3}, [%4];"
        : "=f"(r.x), "=f"(r.y), "=f"(r.z), "=f"(r.w)
        : "l"(p));
    return r;
}

__global__ __launch_bounds__(256) void QPointQuantize_kernel(
    const float4* __restrict__ x,
    const float* __restrict__ q,
    float4* __restrict__ out,
    int n4)
{
    __shared__ float s_qp[16];
    __shared__ float s_mid[16];   // 15 used; banks 0-14, conflict-free

    // One-stage init straight from global q (16 B, L2-resident after warp 0).
    if (threadIdx.x < 16) {
        float qi = q[threadIdx.x];
        s_qp[threadIdx.x] = qi;
        if (threadIdx.x < 15)
            s_mid[threadIdx.x] = 0.5f * (qi + q[threadIdx.x + 1]);
    }
    __syncthreads();

    const float m7 = s_mid[7];    // uniform -> register, skips one LDS level

    // 2 float4 per thread, coalesced, front-batched loads (MLP_p1=2).
    int base = blockIdx.x * (256 * 2) + threadIdx.x;

    if (base + 256 < n4) {        // taken by every live block for this shape
        float4 v0 = ldg128_noL1(&x[base]);
        float4 v1 = ldg128_noL1(&x[base + 256]);

        float4 o0, o1;
        o0.x = quant1(v0.x, m7, s_mid, s_qp);
        o0.y = quant1(v0.y, m7, s_mid, s_qp);
        o0.z = quant1(v0.z, m7, s_mid, s_qp);
        o0.w = quant1(v0.w, m7, s_mid, s_qp);
        o1.x = quant1(v1.x, m7, s_mid, s_qp);
        o1.y = quant1(v1.y, m7, s_mid, s_qp);
        o1.z = quant1(v1.z, m7, s_mid, s_qp);
        o1.w = quant1(v1.w, m7, s_mid, s_qp);

        __stcs(&out[base],       o0);
        __stcs(&out[base + 256], o1);
    } else {
        // Cold tail fallback (unreached for 64x1024x1024, kept for safety)
        for (int k = 0; k < 2; k++) {
            int idx = base + k * 256;
            if (idx < n4) {
                float4 v = ldg128_noL1(&x[idx]);
                float4 o;
                o.x = quant1(v.x, m7, s_mid, s_qp);
                o.y = quant1(v.y, m7, s_mid, s_qp);
                o.z = quant1(v.z, m7, s_mid, s_qp);
                o.w = quant1(v.w, m7, s_mid, s_qp);
                __stcs(&out[idx], o);
            }
        }
    }
}

extern "C" void kernel_launch(void* const* d_in, const int* in_sizes, int n_in,
                              void* d_out, int out_size)
{
    const float* x = (const float*)d_in[0];   // (64, 1024, 1024) fp32
    const float* q = (const float*)d_in[1];   // (16,) fp32 sorted
    float* out = (float*)d_out;

    int n = in_sizes[0];          // 67,108,864
    int n4 = n >> 2;              // 16,777,216 float4s

    int threads = 256;
    int elems_per_block = threads * 2;                     // 512 float4s
    int blocks = (n4 + elems_per_block - 1) / elems_per_block;  // 32,768

    QPointQuantize_kernel<<<blocks, threads>>>(
        (const float4*)x, q, (float4*)out, n4);
}

// round 14
// speedup vs baseline: 1.2366x; 1.0004x over previous
#include <cuda_runtime.h>
#include <cuda_bf16.h>
#include <cstdint>

// Nearest-of-16-sorted-qpoints quantizer, round 11 (terminal probe).
// R10 = best (80.38us bench / 77.82us ncu, DRAM 78.7%). Floor model:
// 512 MiB irreducible r+w traffic at the mixed-stream HBM3e ceiling.
// R11: add L1::no_allocate to the STORE side as well (write-once data
// should not write-allocate in L1). Otherwise byte-identical to R10.

__device__ __forceinline__ float quant1(float v, float m7,
                                        const float* __restrict__ s_mid,
                                        const float* __restrict__ s_qp)
{
    int i = (v > m7) ? 8 : 0;              // level 0: uniform register compare
    i += (v > s_mid[i + 3]) ? 4 : 0;       // level 1: LDS
    i += (v > s_mid[i + 1]) ? 2 : 0;       // level 2: LDS
    i += (v > s_mid[i]) ? 1 : 0;           // level 3: LDS
    return s_qp[i];                         // value LUT: LDS broadcast
}

// 128-bit streaming load, no L1 allocation.
__device__ __forceinline__ float4 ldg128_noL1(const float4* p)
{
    float4 r;
    asm volatile(
        "ld.global.L1::no_allocate.v4.f32 {%0,%1,%2,%3}, [%4];"
        : "=f"(r.x), "=f"(r.y), "=f"(r.z), "=f"(r.w)
        : "l"(p));
    return r;
}

// 128-bit streaming store, no L1 allocation.
__device__ __forceinline__ void stg128_noL1(float4* p, float4 v)
{
    asm volatile(
        "st.global.L1::no_allocate.v4.f32 [%0], {%1,%2,%3,%4};"
        :: "l"(p), "f"(v.x), "f"(v.y), "f"(v.z), "f"(v.w)
        : "memory");
}

__global__ __launch_bounds__(256) void QPointQuantize_kernel(
    const float4* __restrict__ x,
    const float* __restrict__ q,
    float4* __restrict__ out,
    int n4)
{
    __shared__ float s_qp[16];
    __shared__ float s_mid[16];   // 15 used; banks 0-14, conflict-free

    // One-stage init straight from global q (16 B, L2-resident after warp 0).
    if (threadIdx.x < 16) {
        float qi = q[threadIdx.x];
        s_qp[threadIdx.x] = qi;
        if (threadIdx.x < 15)
            s_mid[threadIdx.x] = 0.5f * (qi + q[threadIdx.x + 1]);
    }
    __syncthreads();

    const float m7 = s_mid[7];    // uniform -> register, skips one LDS level

    // 2 float4 per thread, coalesced, front-batched loads (MLP_p1=2).
    int base = blockIdx.x * (256 * 2) + threadIdx.x;

    if (base + 256 < n4) {        // taken by every live block for this shape
        float4 v0 = ldg128_noL1(&x[base]);
        float4 v1 = ldg128_noL1(&x[base + 256]);

        float4 o0, o1;
        o0.x = quant1(v0.x, m7, s_mid, s_qp);
        o0.y = quant1(v0.y, m7, s_mid, s_qp);
        o0.z = quant1(v0.z, m7, s_mid, s_qp);
        o0.w = quant1(v0.w, m7, s_mid, s_qp);
        o1.x = quant1(v1.x, m7, s_mid, s_qp);
        o1.y = quant1(v1.y, m7, s_mid, s_qp);
        o1.z = quant1(v1.z, m7, s_mid, s_qp);
        o1.w = quant1(v1.w, m7, s_mid, s_qp);

        stg128_noL1(&out[base],       o0);
        stg128_noL1(&out[base + 256], o1);
    } else {
        // Cold tail fallback (unreached for 64x1024x1024, kept for safety)
        for (int k = 0; k < 2; k++) {
            int idx = base + k * 256;
            if (idx < n4) {
                float4 v = ldg128_noL1(&x[idx]);
                float4 o;
                o.x = quant1(v.x, m7, s_mid, s_qp);
                o.y = quant1(v.y, m7, s_mid, s_qp);
                o.z = quant1(v.z, m7, s_mid, s_qp);
                o.w = quant1(v.w, m7, s_mid, s_qp);
                stg128_noL1(&out[idx], o);
            }
        }
    }
}

extern "C" void kernel_launch(void* const* d_in, const int* in_sizes, int n_in,
                              void* d_out, int out_size)
{
    const float* x = (const float*)d_in[0];   // (64, 1024, 1024) fp32
    const float* q = (const float*)d_in[1];   // (16,) fp32 sorted
    float* out = (float*)d_out;

    int n = in_sizes[0];          // 67,108,864
    int n4 = n >> 2;              // 16,777,216 float4s

    int threads = 256;
    int elems_per_block = threads * 2;                     // 512 float4s
    int blocks = (n4 + elems_per_block - 1) / elems_per_block;  // 32,768

    QPointQuantize_kernel<<<blocks, threads>>>(
        (const float4*)x, q, (float4*)out, n4);
}